// round 1
// baseline (speedup 1.0000x reference)
#include <cuda_runtime.h>
#include <math.h>
#include <stddef.h>

// Problem constants
#define NB 2
#define NT 2048
#define ND 1024
#define NH 8
#define KDIM 128
#define VDIM 256
#define NTOK (NB*NT)       // 4096
#define KEYDIM 1024
#define VALDIM 2048

// ---------------------------------------------------------------------------
// Scratch (static device globals; no allocation in kernel_launch)
// ---------------------------------------------------------------------------
__device__ float g_qpre[(size_t)NTOK*KEYDIM];
__device__ float g_kpre[(size_t)NTOK*KEYDIM];
__device__ float g_vpre[(size_t)NTOK*VALDIM];
__device__ float g_q   [(size_t)NTOK*KEYDIM];
__device__ float g_k   [(size_t)NTOK*KEYDIM];
__device__ float g_v   [(size_t)NTOK*VALDIM];
__device__ float g_gate[(size_t)NTOK*VALDIM];
__device__ float g_o   [(size_t)NTOK*VALDIM];
__device__ float g_apre[(size_t)NTOK*NH];
__device__ float g_bpre[(size_t)NTOK*NH];
__device__ float g_alpha[(size_t)NTOK*NH];
__device__ float g_beta [(size_t)NTOK*NH];

// ---------------------------------------------------------------------------
// fp32 tiled GEMM: C[M,N] = A[M,K] * B[K,N], all row-major.
// 128x128 tile, BK=16, 256 threads, 8x8 per-thread microtile.
// M, K assumed multiples of 128/16; N guarded (handles N=8).
// ---------------------------------------------------------------------------
__global__ __launch_bounds__(256) void gemm_f32(
    const float* __restrict__ A, const float* __restrict__ Bm,
    float* __restrict__ C, int M, int N, int K)
{
    const int BM = 128, BN = 128, BK = 16;
    __shared__ float As[16][132];
    __shared__ float Bs[16][132];

    int tid = threadIdx.x;
    int tx = tid & 15;        // 0..15 -> output cols tx*8
    int ty = tid >> 4;        // 0..15 -> output rows ty*8
    int m0 = blockIdx.y * BM;
    int n0 = blockIdx.x * BN;

    float acc[8][8];
#pragma unroll
    for (int i = 0; i < 8; i++)
#pragma unroll
        for (int j = 0; j < 8; j++) acc[i][j] = 0.f;

    for (int k0 = 0; k0 < K; k0 += BK) {
        // Load A tile: 128x16 = 512 float4, 2 per thread; store transposed As[k][m]
#pragma unroll
        for (int l = 0; l < 2; l++) {
            int id  = tid + l*256;           // 0..511
            int row = id >> 2;               // 0..127
            int kq  = (id & 3) * 4;          // 0,4,8,12
            float4 va = *(const float4*)&A[(size_t)(m0+row)*K + k0 + kq];
            As[kq+0][row] = va.x;
            As[kq+1][row] = va.y;
            As[kq+2][row] = va.z;
            As[kq+3][row] = va.w;
        }
        // Load B tile: 16x128 = 512 float4, 2 per thread; Bs[k][n]
#pragma unroll
        for (int l = 0; l < 2; l++) {
            int id = tid + l*256;
            int kk = id >> 5;                // 0..15
            int nq = (id & 31) * 4;          // 0..124
            float4 vb = make_float4(0.f,0.f,0.f,0.f);
            if (n0 + nq < N)
                vb = *(const float4*)&Bm[(size_t)(k0+kk)*N + n0 + nq];
            *(float4*)&Bs[kk][nq] = vb;
        }
        __syncthreads();

#pragma unroll
        for (int kk = 0; kk < BK; kk++) {
            float a[8], b[8];
            *(float4*)&a[0] = *(const float4*)&As[kk][ty*8];
            *(float4*)&a[4] = *(const float4*)&As[kk][ty*8+4];
            *(float4*)&b[0] = *(const float4*)&Bs[kk][tx*8];
            *(float4*)&b[4] = *(const float4*)&Bs[kk][tx*8+4];
#pragma unroll
            for (int i = 0; i < 8; i++)
#pragma unroll
                for (int j = 0; j < 8; j++)
                    acc[i][j] += a[i]*b[j];
        }
        __syncthreads();
    }

#pragma unroll
    for (int i = 0; i < 8; i++) {
        int row = m0 + ty*8 + i;
#pragma unroll
        for (int j = 0; j < 8; j += 4) {
            int col = n0 + tx*8 + j;
            if (col < N)
                *(float4*)&C[(size_t)row*N + col] =
                    make_float4(acc[i][j], acc[i][j+1], acc[i][j+2], acc[i][j+3]);
        }
    }
}

// ---------------------------------------------------------------------------
// alpha/beta epilogue: alpha = exp(-exp(A_log[h]) * softplus(apre + dt_bias[h]))
//                      beta  = 2*sigmoid(bpre)
// ---------------------------------------------------------------------------
__global__ void ab_kernel(const float* __restrict__ apre,
                          const float* __restrict__ bpre,
                          const float* __restrict__ A_log,
                          const float* __restrict__ dt_bias,
                          float* __restrict__ alpha,
                          float* __restrict__ beta)
{
    int i = blockIdx.x * blockDim.x + threadIdx.x;
    if (i >= NTOK*NH) return;
    int h = i & (NH-1);
    float xv = apre[i] + dt_bias[h];
    float sp = (xv > 20.f) ? xv : log1pf(expf(xv));
    alpha[i] = expf(-expf(A_log[h]) * sp);
    float bv = bpre[i];
    beta[i] = 2.f / (1.f + expf(-bv));
}

// ---------------------------------------------------------------------------
// Causal depthwise conv (KS=4) + SiLU (+ optional per-head l2norm over 128 ch)
// One block per token; blockDim = C/4 threads; each thread 4 channels.
// For NORM (C=1024): warp w covers channels [128w,128w+128) = head w exactly.
// ---------------------------------------------------------------------------
template<int C, bool NORM>
__global__ void conv_silu_kernel(const float* __restrict__ xin,
                                 const float* __restrict__ w,
                                 float* __restrict__ out)
{
    int t  = blockIdx.x;           // global token
    int tt = t & (NT-1);           // token within batch
    int c4 = threadIdx.x * 4;

    float wc[4][4];
    *(float4*)wc[0] = *(const float4*)&w[(c4+0)*4];
    *(float4*)wc[1] = *(const float4*)&w[(c4+1)*4];
    *(float4*)wc[2] = *(const float4*)&w[(c4+2)*4];
    *(float4*)wc[3] = *(const float4*)&w[(c4+3)*4];

    float acc[4] = {0.f, 0.f, 0.f, 0.f};
#pragma unroll
    for (int j = 0; j < 4; j++) {
        int ts = tt - 3 + j;
        if (ts >= 0) {
            float xr[4];
            *(float4*)xr = *(const float4*)&xin[(size_t)(t-3+j)*C + c4];
#pragma unroll
            for (int ci = 0; ci < 4; ci++)
                acc[ci] += wc[ci][j] * xr[ci];
        }
    }
    float y[4];
#pragma unroll
    for (int ci = 0; ci < 4; ci++) {
        float z = acc[ci];
        y[ci] = z / (1.f + expf(-z));
    }
    if (NORM) {
        float ss = y[0]*y[0] + y[1]*y[1] + y[2]*y[2] + y[3]*y[3];
#pragma unroll
        for (int off = 16; off > 0; off >>= 1)
            ss += __shfl_xor_sync(0xffffffffu, ss, off);
        float n  = sqrtf(ss);
        float sc = 1.f / fmaxf(n, 1e-6f);
#pragma unroll
        for (int ci = 0; ci < 4; ci++) y[ci] *= sc;
    }
    *(float4*)&out[(size_t)t*C + c4] = make_float4(y[0], y[1], y[2], y[3]);
}

// ---------------------------------------------------------------------------
// Gated delta-rule scan.
// Grid: B*H*8 = 128 CTAs, 128 threads each. CTA owns 32 VD rows of one (b,h).
// 4 threads per row, 32 KD cols each; state lives in registers (32 f/thread).
// Chunked SMEM staging of k,q,v,alpha,beta (32 steps/chunk); no block sync in
// the inner step loop (row reductions are 4-lane shfl butterflies).
// ---------------------------------------------------------------------------
__global__ __launch_bounds__(128, 1) void scan_kernel()
{
    const int blk = blockIdx.x;            // b*64 + h*8 + vb
    const int vb  = blk & 7;
    const int h   = (blk >> 3) & 7;
    const int b   = blk >> 6;
    const int vr0 = vb * 32;

    const int tid = threadIdx.x;
    const int row = tid >> 2;              // 0..31
    const int cg  = tid & 3;               // 0..3 (32 cols each)

    __shared__ float sk[32][128];
    __shared__ float sq[32][128];
    __shared__ float sv[32][32];
    __shared__ float so[32][32];
    __shared__ float sa[32];
    __shared__ float sb2[32];

    float s[32];
#pragma unroll
    for (int j = 0; j < 32; j++) s[j] = 0.f;

    const size_t tok0 = (size_t)b * NT;

    for (int c0 = 0; c0 < NT; c0 += 32) {
        // ---- stage chunk ----
#pragma unroll
        for (int l = 0; l < 8; l++) {
            int id = tid + l*128;          // 0..1023 (32 steps * 32 float4)
            int st = id >> 5;
            int cq = (id & 31) * 4;
            size_t gidx = (tok0 + c0 + st) * (size_t)KEYDIM + h*KDIM + cq;
            *(float4*)&sk[st][cq] = *(const float4*)&g_k[gidx];
            *(float4*)&sq[st][cq] = *(const float4*)&g_q[gidx];
        }
#pragma unroll
        for (int l = 0; l < 2; l++) {
            int id = tid + l*128;          // 0..255 (32 steps * 8 float4)
            int st = id >> 3;
            int vq = (id & 7) * 4;
            *(float4*)&sv[st][vq] =
                *(const float4*)&g_v[(tok0 + c0 + st) * (size_t)VALDIM + h*VDIM + vr0 + vq];
        }
        if (tid < 32)
            sa[tid] = g_alpha[(tok0 + c0 + tid) * NH + h];
        else if (tid < 64)
            sb2[tid-32] = g_beta[(tok0 + c0 + (tid-32)) * NH + h];
        __syncthreads();

        // ---- 32 sequential steps ----
        for (int i = 0; i < 32; i++) {
            float a  = sa[i];
            float bb = sb2[i];
            float vv = sv[i][row];
            float kf[32], qf[32];
            const float* kr = &sk[i][cg*32];
            const float* qr = &sq[i][cg*32];
#pragma unroll
            for (int j = 0; j < 8; j++) {
                *(float4*)&kf[j*4] = *(const float4*)&kr[j*4];
                *(float4*)&qf[j*4] = *(const float4*)&qr[j*4];
            }
            float r = 0.f;
#pragma unroll
            for (int j = 0; j < 32; j++) r += s[j] * kf[j];
            r += __shfl_xor_sync(0xffffffffu, r, 1);
            r += __shfl_xor_sync(0xffffffffu, r, 2);
            float c = bb*vv - a*bb*r;
            float o = 0.f;
#pragma unroll
            for (int j = 0; j < 32; j++) {
                s[j] = a*s[j] + c*kf[j];
                o += s[j] * qf[j];
            }
            o += __shfl_xor_sync(0xffffffffu, o, 1);
            o += __shfl_xor_sync(0xffffffffu, o, 2);
            if (cg == 0) so[i][row] = o;
        }
        __syncthreads();

        // ---- flush chunk output (coalesced 128B per row group) ----
#pragma unroll
        for (int l = 0; l < 8; l++) {
            int id = tid + l*128;          // 0..1023
            int st = id >> 5;
            int rr = id & 31;
            g_o[(tok0 + c0 + st) * (size_t)VALDIM + h*VDIM + vr0 + rr] = so[st][rr];
        }
        // next iteration's load barrier separates this flush from so re-writes
    }
}

// ---------------------------------------------------------------------------
// Gating epilogue: o = o * rsqrt(mean(o^2)+1e-5) * o_norm_w * silu(gate)
// One block per (token, head); 256 threads = VD values.
// ---------------------------------------------------------------------------
__global__ void gate_kernel(float* __restrict__ o,
                            const float* __restrict__ gate,
                            const float* __restrict__ w)
{
    int bh = blockIdx.x;                   // token*8 + h
    size_t base = (size_t)bh * VDIM;
    int tid = threadIdx.x;

    float v  = o[base + tid];
    float ss = v*v;
#pragma unroll
    for (int off = 16; off > 0; off >>= 1)
        ss += __shfl_xor_sync(0xffffffffu, ss, off);
    __shared__ float red[8];
    if ((tid & 31) == 0) red[tid >> 5] = ss;
    __syncthreads();
    float tot = red[0]+red[1]+red[2]+red[3]+red[4]+red[5]+red[6]+red[7];
    float rms = rsqrtf(tot * (1.f/VDIM) + 1e-5f);

    float gv = gate[base + tid];
    float sg = gv / (1.f + expf(-gv));
    o[base + tid] = v * rms * w[tid] * sg;
}

// ---------------------------------------------------------------------------
// launch
// ---------------------------------------------------------------------------
extern "C" void kernel_launch(void* const* d_in, const int* in_sizes, int n_in,
                              void* d_out, int out_size)
{
    const float* x       = (const float*)d_in[0];
    const float* Wq      = (const float*)d_in[1];
    const float* Wk      = (const float*)d_in[2];
    const float* Wv      = (const float*)d_in[3];
    const float* Wa      = (const float*)d_in[4];
    const float* Wb      = (const float*)d_in[5];
    const float* Wg      = (const float*)d_in[6];
    const float* Wo      = (const float*)d_in[7];
    const float* A_log   = (const float*)d_in[8];
    const float* dt_bias = (const float*)d_in[9];
    const float* conv_q  = (const float*)d_in[10];
    const float* conv_k  = (const float*)d_in[11];
    const float* conv_v  = (const float*)d_in[12];
    const float* o_nw    = (const float*)d_in[13];
    float* out = (float*)d_out;

    float *qpre, *kpre, *vpre, *q, *k, *v, *gatep, *obuf;
    float *apre, *bpre, *alpha, *beta;
    cudaGetSymbolAddress((void**)&qpre,  g_qpre);
    cudaGetSymbolAddress((void**)&kpre,  g_kpre);
    cudaGetSymbolAddress((void**)&vpre,  g_vpre);
    cudaGetSymbolAddress((void**)&q,     g_q);
    cudaGetSymbolAddress((void**)&k,     g_k);
    cudaGetSymbolAddress((void**)&v,     g_v);
    cudaGetSymbolAddress((void**)&gatep, g_gate);
    cudaGetSymbolAddress((void**)&obuf,  g_o);
    cudaGetSymbolAddress((void**)&apre,  g_apre);
    cudaGetSymbolAddress((void**)&bpre,  g_bpre);
    cudaGetSymbolAddress((void**)&alpha, g_alpha);
    cudaGetSymbolAddress((void**)&beta,  g_beta);

    dim3 thr(256);
    // Projections
    gemm_f32<<<dim3( 8, 32), thr>>>(x, Wq, qpre,  NTOK, KEYDIM, ND);
    gemm_f32<<<dim3( 8, 32), thr>>>(x, Wk, kpre,  NTOK, KEYDIM, ND);
    gemm_f32<<<dim3(16, 32), thr>>>(x, Wv, vpre,  NTOK, VALDIM, ND);
    gemm_f32<<<dim3(16, 32), thr>>>(x, Wg, gatep, NTOK, VALDIM, ND);
    gemm_f32<<<dim3( 1, 32), thr>>>(x, Wa, apre,  NTOK, NH, ND);
    gemm_f32<<<dim3( 1, 32), thr>>>(x, Wb, bpre,  NTOK, NH, ND);

    ab_kernel<<<(NTOK*NH + 255)/256, 256>>>(apre, bpre, A_log, dt_bias, alpha, beta);

    conv_silu_kernel<KEYDIM, true ><<<NTOK, KEYDIM/4>>>(qpre, conv_q, q);
    conv_silu_kernel<KEYDIM, true ><<<NTOK, KEYDIM/4>>>(kpre, conv_k, k);
    conv_silu_kernel<VALDIM, false><<<NTOK, VALDIM/4>>>(vpre, conv_v, v);

    scan_kernel<<<NB*NH*8, 128>>>();

    gate_kernel<<<NTOK*NH, VDIM>>>(obuf, gatep, o_nw);

    // Output projection
    gemm_f32<<<dim3(8, 32), thr>>>(obuf, Wo, out, NTOK, ND, VALDIM);
}

// round 4
// speedup vs baseline: 1.3443x; 1.3443x over previous
#include <cuda_runtime.h>
#include <cuda_bf16.h>
#include <math.h>
#include <stddef.h>
#include <stdint.h>

// Problem constants
#define NB 2
#define NT 2048
#define ND 1024
#define NH 8
#define KDIM 128
#define VDIM 256
#define NTOK (NB*NT)       // 4096
#define KEYDIM 1024
#define VALDIM 2048

// ---------------------------------------------------------------------------
// Scratch (static device globals; no allocation in kernel_launch)
// ---------------------------------------------------------------------------
__device__ float g_qpre[(size_t)NTOK*KEYDIM];
__device__ float g_kpre[(size_t)NTOK*KEYDIM];
__device__ float g_vpre[(size_t)NTOK*VALDIM];
__device__ float g_q   [(size_t)NTOK*KEYDIM];
__device__ float g_k   [(size_t)NTOK*KEYDIM];
__device__ float g_v   [(size_t)NTOK*VALDIM];
__device__ float g_gate[(size_t)NTOK*VALDIM];
__device__ float g_o   [(size_t)NTOK*VALDIM];
__device__ float g_apre[(size_t)NTOK*NH];
__device__ float g_bpre[(size_t)NTOK*NH];
__device__ float g_alpha[(size_t)NTOK*NH];
__device__ float g_beta [(size_t)NTOK*NH];

// bf16 hi/lo split scratch for tensor-core GEMMs
__device__ __align__(16) __nv_bfloat16 g_xh[(size_t)NTOK*ND];
__device__ __align__(16) __nv_bfloat16 g_xl[(size_t)NTOK*ND];
__device__ __align__(16) __nv_bfloat16 g_oh[(size_t)NTOK*VALDIM];
__device__ __align__(16) __nv_bfloat16 g_ol[(size_t)NTOK*VALDIM];
// transposed weights [N,K] bf16 hi/lo (reused sequentially per GEMM)
__device__ __align__(16) __nv_bfloat16 g_wth[(size_t)2048*2048];
__device__ __align__(16) __nv_bfloat16 g_wtl[(size_t)2048*2048];

// ---------------------------------------------------------------------------
// helpers
// ---------------------------------------------------------------------------
__device__ __forceinline__ uint32_t smem_u32(const void* p) {
    uint32_t a;
    asm("{ .reg .u64 t; cvta.to.shared.u64 t, %1; cvt.u32.u64 %0, t; }"
        : "=r"(a) : "l"(p));
    return a;
}

#define CP_ASYNC16(dst, src) \
    asm volatile("cp.async.cg.shared.global [%0], [%1], 16;" :: "r"(dst), "l"(src))
#define CP_COMMIT() asm volatile("cp.async.commit_group;")
#define CP_WAIT(n)  asm volatile("cp.async.wait_group %0;" :: "n"(n))

#define LDMX4(r, addr) \
    asm volatile("ldmatrix.sync.aligned.m8n8.x4.shared.b16 {%0,%1,%2,%3}, [%4];" \
        : "=r"((r)[0]), "=r"((r)[1]), "=r"((r)[2]), "=r"((r)[3]) : "r"(addr))

#define MMA_BF16(c, a, b) \
    asm volatile("mma.sync.aligned.m16n8k16.row.col.f32.bf16.bf16.f32 " \
        "{%0,%1,%2,%3}, {%4,%5,%6,%7}, {%8,%9}, {%0,%1,%2,%3};" \
        : "+f"((c)[0]), "+f"((c)[1]), "+f"((c)[2]), "+f"((c)[3]) \
        : "r"((a)[0]), "r"((a)[1]), "r"((a)[2]), "r"((a)[3]), \
          "r"((b)[0]), "r"((b)[1]))

// ---------------------------------------------------------------------------
// Tensor-core GEMM (legacy mma.sync, base sm_100 ISA):
//   C[M,N](f32) = (Ah+Al)[M,K] x (Bh+Bl)[N,K]^T    (bf16 hi/lo, 3 products)
// CTA tile 128x128, BK=32, 256 threads (8 warps = 4m x 2n, warp tile 32x64),
// cp.async 2-stage double buffer, padded smem rows (stride 80B, ldmatrix
// conflict-free: banks 20r mod 32 all distinct).
// ---------------------------------------------------------------------------
#define TILE_B   10240            // 128 rows * 80 bytes
#define STAGE_B  (4*TILE_B)       // Ah, Al, Bh, Bl
#define GEMM_SMEM (2*STAGE_B)     // 81920

__device__ __forceinline__ void g2s_chunk(
    uint32_t dbase, const __nv_bfloat16* Ah, const __nv_bfloat16* Al,
    const __nv_bfloat16* Bh, const __nv_bfloat16* Bl,
    int m0, int n0, int k0, int K, int tid)
{
    const __nv_bfloat16* srcs[4] = {
        Ah + (size_t)m0 * K + k0, Al + (size_t)m0 * K + k0,
        Bh + (size_t)n0 * K + k0, Bl + (size_t)n0 * K + k0 };
#pragma unroll
    for (int t = 0; t < 4; t++) {
        const __nv_bfloat16* src = srcs[t];
        uint32_t db = dbase + t * TILE_B;
#pragma unroll
        for (int l = 0; l < 2; l++) {
            int id  = tid + l * 256;       // 0..511
            int row = id >> 2;             // 0..127
            int q   = id & 3;              // 16B unit (8 bf16)
            CP_ASYNC16(db + row * 80 + q * 16, src + (size_t)row * K + q * 8);
        }
    }
}

__global__ __launch_bounds__(256, 1) void gemm_mma(
    const __nv_bfloat16* __restrict__ Ah, const __nv_bfloat16* __restrict__ Al,
    const __nv_bfloat16* __restrict__ Bh, const __nv_bfloat16* __restrict__ Bl,
    float* __restrict__ C, int M, int N, int K)
{
    extern __shared__ __align__(16) char smem[];
    const uint32_t sbase = smem_u32(smem);
    const int tid  = threadIdx.x;
    const int wid  = tid >> 5, lane = tid & 31;
    const int wm   = wid >> 1, wn = wid & 1;
    const int m0   = blockIdx.y * 128;
    const int n0   = blockIdx.x * 128;

    const int mat = lane >> 3;             // ldmatrix quadrant
    const int r   = lane & 7;

    float acc[2][8][4];
#pragma unroll
    for (int f = 0; f < 2; f++)
#pragma unroll
        for (int p = 0; p < 8; p++)
#pragma unroll
            for (int j = 0; j < 4; j++) acc[f][p][j] = 0.f;

    const int nc = K >> 5;

    // prologue: chunk 0 -> stage 0
    g2s_chunk(sbase, Ah, Al, Bh, Bl, m0, n0, 0, K, tid);
    CP_COMMIT();

    for (int c = 0; c < nc; c++) {
        if (c + 1 < nc) {
            g2s_chunk(sbase + ((c + 1) & 1) * STAGE_B,
                      Ah, Al, Bh, Bl, m0, n0, (c + 1) << 5, K, tid);
            CP_COMMIT();
            CP_WAIT(1);
        } else {
            CP_WAIT(0);
        }
        __syncthreads();

        const uint32_t ab  = sbase + (c & 1) * STAGE_B;          // Ah tile
        const uint32_t alb = ab + TILE_B;
        const uint32_t bhb = ab + 2 * TILE_B;
        const uint32_t blb = ab + 3 * TILE_B;

#pragma unroll
        for (int ks = 0; ks < 2; ks++) {
            uint32_t fa_h[2][4], fa_l[2][4];
#pragma unroll
            for (int f = 0; f < 2; f++) {
                int row  = wm * 32 + f * 16 + ((mat & 1) << 3) + r;
                int kcol = ks * 16 + ((mat >> 1) << 3);
                uint32_t off = row * 80 + kcol * 2;
                LDMX4(fa_h[f], ab  + off);
                LDMX4(fa_l[f], alb + off);
            }
            uint32_t fb_h[8][2], fb_l[8][2];
#pragma unroll
            for (int p = 0; p < 4; p++) {
                int row  = wn * 64 + p * 16 + ((mat >> 1) << 3) + r;
                int kcol = ks * 16 + ((mat & 1) << 3);
                uint32_t off = row * 80 + kcol * 2;
                uint32_t t4[4];
                LDMX4(t4, bhb + off);
                fb_h[p*2][0] = t4[0]; fb_h[p*2][1] = t4[1];
                fb_h[p*2+1][0] = t4[2]; fb_h[p*2+1][1] = t4[3];
                LDMX4(t4, blb + off);
                fb_l[p*2][0] = t4[0]; fb_l[p*2][1] = t4[1];
                fb_l[p*2+1][0] = t4[2]; fb_l[p*2+1][1] = t4[3];
            }
#pragma unroll
            for (int f = 0; f < 2; f++)
#pragma unroll
                for (int p = 0; p < 8; p++) {
                    MMA_BF16(acc[f][p], fa_h[f], fb_h[p]);
                    MMA_BF16(acc[f][p], fa_h[f], fb_l[p]);
                    MMA_BF16(acc[f][p], fa_l[f], fb_h[p]);
                }
        }
        __syncthreads();
    }

    // epilogue
#pragma unroll
    for (int f = 0; f < 2; f++) {
        int row0 = m0 + wm * 32 + f * 16 + (lane >> 2);
#pragma unroll
        for (int p = 0; p < 8; p++) {
            int col = n0 + wn * 64 + p * 8 + (lane & 3) * 2;
            *(float2*)&C[(size_t)row0 * N + col] =
                make_float2(acc[f][p][0], acc[f][p][1]);
            *(float2*)&C[(size_t)(row0 + 8) * N + col] =
                make_float2(acc[f][p][2], acc[f][p][3]);
        }
    }
}

// ---------------------------------------------------------------------------
// fp32 -> bf16 hi/lo elementwise split
// ---------------------------------------------------------------------------
__global__ void cvt_hilo(const float* __restrict__ x,
                         __nv_bfloat16* __restrict__ hi,
                         __nv_bfloat16* __restrict__ lo, int n)
{
    int i = blockIdx.x * blockDim.x + threadIdx.x;
    if (i >= n) return;
    float v = x[i];
    __nv_bfloat16 h = __float2bfloat16(v);
    hi[i] = h;
    lo[i] = __float2bfloat16(v - __bfloat162float(h));
}

// W[K,N] fp32 -> Wt[N,K] bf16 hi/lo (transpose + split)
__global__ void transpose_cvt(const float* __restrict__ W,
                              __nv_bfloat16* __restrict__ Th,
                              __nv_bfloat16* __restrict__ Tl, int K, int N)
{
    __shared__ float tile[32][33];
    int kb = blockIdx.y * 32, nb = blockIdx.x * 32;
    int tx = threadIdx.x, ty = threadIdx.y;
#pragma unroll
    for (int i = ty; i < 32; i += 8)
        tile[i][tx] = W[(size_t)(kb + i) * N + nb + tx];
    __syncthreads();
#pragma unroll
    for (int i = ty; i < 32; i += 8) {
        float v = tile[tx][i];                     // = W[kb+tx][nb+i]
        __nv_bfloat16 h = __float2bfloat16(v);
        size_t oidx = (size_t)(nb + i) * K + kb + tx;
        Th[oidx] = h;
        Tl[oidx] = __float2bfloat16(v - __bfloat162float(h));
    }
}

// ---------------------------------------------------------------------------
// fp32 tiled GEMM (kept for the tiny Wa/Wb projections, N=8)
// ---------------------------------------------------------------------------
__global__ __launch_bounds__(256) void gemm_f32(
    const float* __restrict__ A, const float* __restrict__ Bm,
    float* __restrict__ C, int M, int N, int K)
{
    const int BM = 128, BK = 16;
    __shared__ float As[16][132];
    __shared__ float Bs[16][132];

    int tid = threadIdx.x;
    int tx = tid & 15;
    int ty = tid >> 4;
    int m0 = blockIdx.y * BM;
    int n0 = blockIdx.x * 128;

    float acc[8][8];
#pragma unroll
    for (int i = 0; i < 8; i++)
#pragma unroll
        for (int j = 0; j < 8; j++) acc[i][j] = 0.f;

    for (int k0 = 0; k0 < K; k0 += BK) {
#pragma unroll
        for (int l = 0; l < 2; l++) {
            int id  = tid + l*256;
            int row = id >> 2;
            int kq  = (id & 3) * 4;
            float4 va = *(const float4*)&A[(size_t)(m0+row)*K + k0 + kq];
            As[kq+0][row] = va.x;
            As[kq+1][row] = va.y;
            As[kq+2][row] = va.z;
            As[kq+3][row] = va.w;
        }
#pragma unroll
        for (int l = 0; l < 2; l++) {
            int id = tid + l*256;
            int kk = id >> 5;
            int nq = (id & 31) * 4;
            float4 vb = make_float4(0.f,0.f,0.f,0.f);
            if (n0 + nq < N)
                vb = *(const float4*)&Bm[(size_t)(k0+kk)*N + n0 + nq];
            *(float4*)&Bs[kk][nq] = vb;
        }
        __syncthreads();

#pragma unroll
        for (int kk = 0; kk < BK; kk++) {
            float a[8], b[8];
            *(float4*)&a[0] = *(const float4*)&As[kk][ty*8];
            *(float4*)&a[4] = *(const float4*)&As[kk][ty*8+4];
            *(float4*)&b[0] = *(const float4*)&Bs[kk][tx*8];
            *(float4*)&b[4] = *(const float4*)&Bs[kk][tx*8+4];
#pragma unroll
            for (int i = 0; i < 8; i++)
#pragma unroll
                for (int j = 0; j < 8; j++)
                    acc[i][j] += a[i]*b[j];
        }
        __syncthreads();
    }

#pragma unroll
    for (int i = 0; i < 8; i++) {
        int row = m0 + ty*8 + i;
#pragma unroll
        for (int j = 0; j < 8; j += 4) {
            int col = n0 + tx*8 + j;
            if (col < N)
                *(float4*)&C[(size_t)row*N + col] =
                    make_float4(acc[i][j], acc[i][j+1], acc[i][j+2], acc[i][j+3]);
        }
    }
}

// ---------------------------------------------------------------------------
// alpha/beta epilogue
// ---------------------------------------------------------------------------
__global__ void ab_kernel(const float* __restrict__ apre,
                          const float* __restrict__ bpre,
                          const float* __restrict__ A_log,
                          const float* __restrict__ dt_bias,
                          float* __restrict__ alpha,
                          float* __restrict__ beta)
{
    int i = blockIdx.x * blockDim.x + threadIdx.x;
    if (i >= NTOK*NH) return;
    int h = i & (NH-1);
    float xv = apre[i] + dt_bias[h];
    float sp = (xv > 20.f) ? xv : log1pf(expf(xv));
    alpha[i] = expf(-expf(A_log[h]) * sp);
    float bv = bpre[i];
    beta[i] = 2.f / (1.f + expf(-bv));
}

// ---------------------------------------------------------------------------
// Causal depthwise conv (KS=4) + SiLU (+ optional per-head l2norm)
// ---------------------------------------------------------------------------
template<int C, bool NORM>
__global__ void conv_silu_kernel(const float* __restrict__ xin,
                                 const float* __restrict__ w,
                                 float* __restrict__ out)
{
    int t  = blockIdx.x;
    int tt = t & (NT-1);
    int c4 = threadIdx.x * 4;

    float wc[4][4];
    *(float4*)wc[0] = *(const float4*)&w[(c4+0)*4];
    *(float4*)wc[1] = *(const float4*)&w[(c4+1)*4];
    *(float4*)wc[2] = *(const float4*)&w[(c4+2)*4];
    *(float4*)wc[3] = *(const float4*)&w[(c4+3)*4];

    float acc[4] = {0.f, 0.f, 0.f, 0.f};
#pragma unroll
    for (int j = 0; j < 4; j++) {
        int ts = tt - 3 + j;
        if (ts >= 0) {
            float xr[4];
            *(float4*)xr = *(const float4*)&xin[(size_t)(t-3+j)*C + c4];
#pragma unroll
            for (int ci = 0; ci < 4; ci++)
                acc[ci] += wc[ci][j] * xr[ci];
        }
    }
    float y[4];
#pragma unroll
    for (int ci = 0; ci < 4; ci++) {
        float z = acc[ci];
        y[ci] = z / (1.f + expf(-z));
    }
    if (NORM) {
        float ss = y[0]*y[0] + y[1]*y[1] + y[2]*y[2] + y[3]*y[3];
#pragma unroll
        for (int off = 16; off > 0; off >>= 1)
            ss += __shfl_xor_sync(0xffffffffu, ss, off);
        float n  = sqrtf(ss);
        float sc = 1.f / fmaxf(n, 1e-6f);
#pragma unroll
        for (int ci = 0; ci < 4; ci++) y[ci] *= sc;
    }
    *(float4*)&out[(size_t)t*C + c4] = make_float4(y[0], y[1], y[2], y[3]);
}

// ---------------------------------------------------------------------------
// Gated delta-rule scan
// ---------------------------------------------------------------------------
__global__ __launch_bounds__(128, 1) void scan_kernel()
{
    const int blk = blockIdx.x;
    const int vb  = blk & 7;
    const int h   = (blk >> 3) & 7;
    const int b   = blk >> 6;
    const int vr0 = vb * 32;

    const int tid = threadIdx.x;
    const int row = tid >> 2;
    const int cg  = tid & 3;

    __shared__ float sk[32][128];
    __shared__ float sq[32][128];
    __shared__ float sv[32][32];
    __shared__ float so[32][32];
    __shared__ float sa[32];
    __shared__ float sb2[32];

    float s[32];
#pragma unroll
    for (int j = 0; j < 32; j++) s[j] = 0.f;

    const size_t tok0 = (size_t)b * NT;

    for (int c0 = 0; c0 < NT; c0 += 32) {
#pragma unroll
        for (int l = 0; l < 8; l++) {
            int id = tid + l*128;
            int st = id >> 5;
            int cq = (id & 31) * 4;
            size_t gidx = (tok0 + c0 + st) * (size_t)KEYDIM + h*KDIM + cq;
            *(float4*)&sk[st][cq] = *(const float4*)&g_k[gidx];
            *(float4*)&sq[st][cq] = *(const float4*)&g_q[gidx];
        }
#pragma unroll
        for (int l = 0; l < 2; l++) {
            int id = tid + l*128;
            int st = id >> 3;
            int vq = (id & 7) * 4;
            *(float4*)&sv[st][vq] =
                *(const float4*)&g_v[(tok0 + c0 + st) * (size_t)VALDIM + h*VDIM + vr0 + vq];
        }
        if (tid < 32)
            sa[tid] = g_alpha[(tok0 + c0 + tid) * NH + h];
        else if (tid < 64)
            sb2[tid-32] = g_beta[(tok0 + c0 + (tid-32)) * NH + h];
        __syncthreads();

        for (int i = 0; i < 32; i++) {
            float a  = sa[i];
            float bb = sb2[i];
            float vv = sv[i][row];
            float kf[32], qf[32];
            const float* kr = &sk[i][cg*32];
            const float* qr = &sq[i][cg*32];
#pragma unroll
            for (int j = 0; j < 8; j++) {
                *(float4*)&kf[j*4] = *(const float4*)&kr[j*4];
                *(float4*)&qf[j*4] = *(const float4*)&qr[j*4];
            }
            float r = 0.f;
#pragma unroll
            for (int j = 0; j < 32; j++) r += s[j] * kf[j];
            r += __shfl_xor_sync(0xffffffffu, r, 1);
            r += __shfl_xor_sync(0xffffffffu, r, 2);
            float c = bb*vv - a*bb*r;
            float o = 0.f;
#pragma unroll
            for (int j = 0; j < 32; j++) {
                s[j] = a*s[j] + c*kf[j];
                o += s[j] * qf[j];
            }
            o += __shfl_xor_sync(0xffffffffu, o, 1);
            o += __shfl_xor_sync(0xffffffffu, o, 2);
            if (cg == 0) so[i][row] = o;
        }
        __syncthreads();

#pragma unroll
        for (int l = 0; l < 8; l++) {
            int id = tid + l*128;
            int st = id >> 5;
            int rr = id & 31;
            g_o[(tok0 + c0 + st) * (size_t)VALDIM + h*VDIM + vr0 + rr] = so[st][rr];
        }
    }
}

// ---------------------------------------------------------------------------
// Gating epilogue
// ---------------------------------------------------------------------------
__global__ void gate_kernel(float* __restrict__ o,
                            const float* __restrict__ gate,
                            const float* __restrict__ w)
{
    int bh = blockIdx.x;
    size_t base = (size_t)bh * VDIM;
    int tid = threadIdx.x;

    float v  = o[base + tid];
    float ss = v*v;
#pragma unroll
    for (int off = 16; off > 0; off >>= 1)
        ss += __shfl_xor_sync(0xffffffffu, ss, off);
    __shared__ float red[8];
    if ((tid & 31) == 0) red[tid >> 5] = ss;
    __syncthreads();
    float tot = red[0]+red[1]+red[2]+red[3]+red[4]+red[5]+red[6]+red[7];
    float rms = rsqrtf(tot * (1.f/VDIM) + 1e-5f);

    float gv = gate[base + tid];
    float sg = gv / (1.f + expf(-gv));
    o[base + tid] = v * rms * w[tid] * sg;
}

// ---------------------------------------------------------------------------
// launch
// ---------------------------------------------------------------------------
extern "C" void kernel_launch(void* const* d_in, const int* in_sizes, int n_in,
                              void* d_out, int out_size)
{
    const float* x       = (const float*)d_in[0];
    const float* Wq      = (const float*)d_in[1];
    const float* Wk      = (const float*)d_in[2];
    const float* Wv      = (const float*)d_in[3];
    const float* Wa      = (const float*)d_in[4];
    const float* Wb      = (const float*)d_in[5];
    const float* Wg      = (const float*)d_in[6];
    const float* Wo      = (const float*)d_in[7];
    const float* A_log   = (const float*)d_in[8];
    const float* dt_bias = (const float*)d_in[9];
    const float* conv_q  = (const float*)d_in[10];
    const float* conv_k  = (const float*)d_in[11];
    const float* conv_v  = (const float*)d_in[12];
    const float* o_nw    = (const float*)d_in[13];
    float* out = (float*)d_out;

    float *qpre, *kpre, *vpre, *gatep, *obuf;
    float *apre, *bpre, *alpha, *beta;
    __nv_bfloat16 *xh, *xl, *oh, *ol, *wth, *wtl;
    cudaGetSymbolAddress((void**)&qpre,  g_qpre);
    cudaGetSymbolAddress((void**)&kpre,  g_kpre);
    cudaGetSymbolAddress((void**)&vpre,  g_vpre);
    cudaGetSymbolAddress((void**)&gatep, g_gate);
    cudaGetSymbolAddress((void**)&obuf,  g_o);
    cudaGetSymbolAddress((void**)&apre,  g_apre);
    cudaGetSymbolAddress((void**)&bpre,  g_bpre);
    cudaGetSymbolAddress((void**)&alpha, g_alpha);
    cudaGetSymbolAddress((void**)&beta,  g_beta);
    cudaGetSymbolAddress((void**)&xh,    g_xh);
    cudaGetSymbolAddress((void**)&xl,    g_xl);
    cudaGetSymbolAddress((void**)&oh,    g_oh);
    cudaGetSymbolAddress((void**)&ol,    g_ol);
    cudaGetSymbolAddress((void**)&wth,   g_wth);
    cudaGetSymbolAddress((void**)&wtl,   g_wtl);
    float *q, *k, *v;
    cudaGetSymbolAddress((void**)&q, g_q);
    cudaGetSymbolAddress((void**)&k, g_k);
    cudaGetSymbolAddress((void**)&v, g_v);

    cudaFuncSetAttribute(gemm_mma, cudaFuncAttributeMaxDynamicSharedMemorySize,
                         GEMM_SMEM);

    dim3 thr(256);
    dim3 tb(32, 8);

    // Split x into bf16 hi/lo
    cvt_hilo<<<(NTOK*ND + 255)/256, 256>>>(x, xh, xl, NTOK*ND);

    // Wq projection  (Wt buffers reused sequentially; stream order serializes)
    transpose_cvt<<<dim3(KEYDIM/32, ND/32), tb>>>(Wq, wth, wtl, ND, KEYDIM);
    gemm_mma<<<dim3(KEYDIM/128, NTOK/128), 256, GEMM_SMEM>>>(
        xh, xl, wth, wtl, qpre, NTOK, KEYDIM, ND);
    // Wk
    transpose_cvt<<<dim3(KEYDIM/32, ND/32), tb>>>(Wk, wth, wtl, ND, KEYDIM);
    gemm_mma<<<dim3(KEYDIM/128, NTOK/128), 256, GEMM_SMEM>>>(
        xh, xl, wth, wtl, kpre, NTOK, KEYDIM, ND);
    // Wv
    transpose_cvt<<<dim3(VALDIM/32, ND/32), tb>>>(Wv, wth, wtl, ND, VALDIM);
    gemm_mma<<<dim3(VALDIM/128, NTOK/128), 256, GEMM_SMEM>>>(
        xh, xl, wth, wtl, vpre, NTOK, VALDIM, ND);
    // Wg
    transpose_cvt<<<dim3(VALDIM/32, ND/32), tb>>>(Wg, wth, wtl, ND, VALDIM);
    gemm_mma<<<dim3(VALDIM/128, NTOK/128), 256, GEMM_SMEM>>>(
        xh, xl, wth, wtl, gatep, NTOK, VALDIM, ND);

    // Small projections (N=8) stay fp32 SIMT
    gemm_f32<<<dim3(1, 32), thr>>>(x, Wa, apre, NTOK, NH, ND);
    gemm_f32<<<dim3(1, 32), thr>>>(x, Wb, bpre, NTOK, NH, ND);

    ab_kernel<<<(NTOK*NH + 255)/256, 256>>>(apre, bpre, A_log, dt_bias, alpha, beta);

    conv_silu_kernel<KEYDIM, true ><<<NTOK, KEYDIM/4>>>(qpre, conv_q, q);
    conv_silu_kernel<KEYDIM, true ><<<NTOK, KEYDIM/4>>>(kpre, conv_k, k);
    conv_silu_kernel<VALDIM, false><<<NTOK, VALDIM/4>>>(vpre, conv_v, v);

    scan_kernel<<<NB*NH*8, 128>>>();

    gate_kernel<<<NTOK*NH, VDIM>>>(obuf, gatep, o_nw);

    // Output projection on tensor cores
    cvt_hilo<<<(NTOK*VALDIM + 255)/256, 256>>>(obuf, oh, ol, NTOK*VALDIM);
    transpose_cvt<<<dim3(ND/32, VALDIM/32), tb>>>(Wo, wth, wtl, VALDIM, ND);
    gemm_mma<<<dim3(ND/128, NTOK/128), 256, GEMM_SMEM>>>(
        oh, ol, wth, wtl, out, NTOK, ND, VALDIM);
}

// round 5
// speedup vs baseline: 1.5346x; 1.1416x over previous
#include <cuda_runtime.h>
#include <cuda_bf16.h>
#include <math.h>
#include <stddef.h>
#include <stdint.h>

// Problem constants
#define NB 2
#define NT 2048
#define ND 1024
#define NH 8
#define KDIM 128
#define VDIM 256
#define NTOK (NB*NT)       // 4096
#define KEYDIM 1024
#define VALDIM 2048
#define NPROJ 6144         // q(1024) | k(1024) | v(2048) | g(2048)

// ---------------------------------------------------------------------------
// Scratch (static device globals; no allocation in kernel_launch)
// ---------------------------------------------------------------------------
__device__ float g_qpre[(size_t)NTOK*KEYDIM];
__device__ float g_kpre[(size_t)NTOK*KEYDIM];
__device__ float g_vpre[(size_t)NTOK*VALDIM];
__device__ float g_q   [(size_t)NTOK*KEYDIM];
__device__ float g_k   [(size_t)NTOK*KEYDIM];
__device__ float g_v   [(size_t)NTOK*VALDIM];
__device__ float g_gate[(size_t)NTOK*VALDIM];
__device__ float g_o   [(size_t)NTOK*VALDIM];
__device__ float g_apre[(size_t)NTOK*NH];
__device__ float g_bpre[(size_t)NTOK*NH];
__device__ float g_alpha[(size_t)NTOK*NH];
__device__ float g_beta [(size_t)NTOK*NH];
__device__ float g_wtab [(size_t)16*ND];

// bf16 hi/lo split scratch for tensor-core GEMMs
__device__ __align__(16) __nv_bfloat16 g_xh[(size_t)NTOK*ND];
__device__ __align__(16) __nv_bfloat16 g_xl[(size_t)NTOK*ND];
__device__ __align__(16) __nv_bfloat16 g_oh[(size_t)NTOK*VALDIM];
__device__ __align__(16) __nv_bfloat16 g_ol[(size_t)NTOK*VALDIM];
// transposed weights [N,K] bf16 hi/lo; sized for fused proj (6144x1024)
__device__ __align__(16) __nv_bfloat16 g_wth[(size_t)NPROJ*ND];
__device__ __align__(16) __nv_bfloat16 g_wtl[(size_t)NPROJ*ND];

// ---------------------------------------------------------------------------
// helpers
// ---------------------------------------------------------------------------
__device__ __forceinline__ uint32_t smem_u32(const void* p) {
    uint32_t a;
    asm("{ .reg .u64 t; cvta.to.shared.u64 t, %1; cvt.u32.u64 %0, t; }"
        : "=r"(a) : "l"(p));
    return a;
}

#define CP_ASYNC16(dst, src) \
    asm volatile("cp.async.cg.shared.global [%0], [%1], 16;" :: "r"(dst), "l"(src))
#define CP_COMMIT() asm volatile("cp.async.commit_group;")
#define CP_WAIT(n)  asm volatile("cp.async.wait_group %0;" :: "n"(n))

#define LDMX4(r, addr) \
    asm volatile("ldmatrix.sync.aligned.m8n8.x4.shared.b16 {%0,%1,%2,%3}, [%4];" \
        : "=r"((r)[0]), "=r"((r)[1]), "=r"((r)[2]), "=r"((r)[3]) : "r"(addr))

#define MMA_BF16(c, a, b) \
    asm volatile("mma.sync.aligned.m16n8k16.row.col.f32.bf16.bf16.f32 " \
        "{%0,%1,%2,%3}, {%4,%5,%6,%7}, {%8,%9}, {%0,%1,%2,%3};" \
        : "+f"((c)[0]), "+f"((c)[1]), "+f"((c)[2]), "+f"((c)[3]) \
        : "r"((a)[0]), "r"((a)[1]), "r"((a)[2]), "r"((a)[3]), \
          "r"((b)[0]), "r"((b)[1]))

// ---------------------------------------------------------------------------
// Tensor-core GEMM (legacy mma.sync, base sm_100 ISA):
//   C = (Ah+Al)[M,K] x (Bh+Bl)[N,K]^T   (bf16 hi/lo, 3 products)
// CTA tile 128x128, BK=32, 256 threads (8 warps = 4m x 2n, warp tile 32x64),
// cp.async 2-stage double buffer, 80B smem row stride (ldmatrix conflict-free).
// FUSED=1: epilogue routes 128-col tiles to 4 destination buffers
// (q|k|v|g concatenated along N).
// ---------------------------------------------------------------------------
#define TILE_B   10240            // 128 rows * 80 bytes
#define STAGE_B  (4*TILE_B)       // Ah, Al, Bh, Bl
#define GEMM_SMEM (2*STAGE_B)     // 81920

__device__ __forceinline__ void g2s_chunk(
    uint32_t dbase, const __nv_bfloat16* Ah, const __nv_bfloat16* Al,
    const __nv_bfloat16* Bh, const __nv_bfloat16* Bl,
    int m0, int n0, int k0, int K, int tid)
{
    const __nv_bfloat16* srcs[4] = {
        Ah + (size_t)m0 * K + k0, Al + (size_t)m0 * K + k0,
        Bh + (size_t)n0 * K + k0, Bl + (size_t)n0 * K + k0 };
#pragma unroll
    for (int t = 0; t < 4; t++) {
        const __nv_bfloat16* src = srcs[t];
        uint32_t db = dbase + t * TILE_B;
#pragma unroll
        for (int l = 0; l < 2; l++) {
            int id  = tid + l * 256;       // 0..511
            int row = id >> 2;             // 0..127
            int q   = id & 3;              // 16B unit (8 bf16)
            CP_ASYNC16(db + row * 80 + q * 16, src + (size_t)row * K + q * 8);
        }
    }
}

template<int FUSED>
__global__ __launch_bounds__(256, 1) void gemm_mma(
    const __nv_bfloat16* __restrict__ Ah, const __nv_bfloat16* __restrict__ Al,
    const __nv_bfloat16* __restrict__ Bh, const __nv_bfloat16* __restrict__ Bl,
    float* __restrict__ C0, float* __restrict__ C1,
    float* __restrict__ C2, float* __restrict__ C3,
    int Nsingle, int K)
{
    extern __shared__ __align__(16) char smem[];
    const uint32_t sbase = smem_u32(smem);
    const int tid  = threadIdx.x;
    const int wid  = tid >> 5, lane = tid & 31;
    const int wm   = wid >> 1, wn = wid & 1;
    const int m0   = blockIdx.y * 128;
    const int n0   = blockIdx.x * 128;

    const int mat = lane >> 3;             // ldmatrix quadrant
    const int r   = lane & 7;

    float acc[2][8][4];
#pragma unroll
    for (int f = 0; f < 2; f++)
#pragma unroll
        for (int p = 0; p < 8; p++)
#pragma unroll
            for (int j = 0; j < 4; j++) acc[f][p][j] = 0.f;

    const int nc = K >> 5;

    g2s_chunk(sbase, Ah, Al, Bh, Bl, m0, n0, 0, K, tid);
    CP_COMMIT();

    for (int c = 0; c < nc; c++) {
        if (c + 1 < nc) {
            g2s_chunk(sbase + ((c + 1) & 1) * STAGE_B,
                      Ah, Al, Bh, Bl, m0, n0, (c + 1) << 5, K, tid);
            CP_COMMIT();
            CP_WAIT(1);
        } else {
            CP_WAIT(0);
        }
        __syncthreads();

        const uint32_t ab  = sbase + (c & 1) * STAGE_B;          // Ah tile
        const uint32_t alb = ab + TILE_B;
        const uint32_t bhb = ab + 2 * TILE_B;
        const uint32_t blb = ab + 3 * TILE_B;

#pragma unroll
        for (int ks = 0; ks < 2; ks++) {
            uint32_t fa_h[2][4], fa_l[2][4];
#pragma unroll
            for (int f = 0; f < 2; f++) {
                int row  = wm * 32 + f * 16 + ((mat & 1) << 3) + r;
                int kcol = ks * 16 + ((mat >> 1) << 3);
                uint32_t off = row * 80 + kcol * 2;
                LDMX4(fa_h[f], ab  + off);
                LDMX4(fa_l[f], alb + off);
            }
            uint32_t fb_h[8][2], fb_l[8][2];
#pragma unroll
            for (int p = 0; p < 4; p++) {
                int row  = wn * 64 + p * 16 + ((mat >> 1) << 3) + r;
                int kcol = ks * 16 + ((mat & 1) << 3);
                uint32_t off = row * 80 + kcol * 2;
                uint32_t t4[4];
                LDMX4(t4, bhb + off);
                fb_h[p*2][0] = t4[0]; fb_h[p*2][1] = t4[1];
                fb_h[p*2+1][0] = t4[2]; fb_h[p*2+1][1] = t4[3];
                LDMX4(t4, blb + off);
                fb_l[p*2][0] = t4[0]; fb_l[p*2][1] = t4[1];
                fb_l[p*2+1][0] = t4[2]; fb_l[p*2+1][1] = t4[3];
            }
#pragma unroll
            for (int f = 0; f < 2; f++)
#pragma unroll
                for (int p = 0; p < 8; p++) {
                    MMA_BF16(acc[f][p], fa_h[f], fb_h[p]);
                    MMA_BF16(acc[f][p], fa_h[f], fb_l[p]);
                    MMA_BF16(acc[f][p], fa_l[f], fb_h[p]);
                }
        }
        __syncthreads();
    }

    // epilogue: pick destination buffer / ld / column base
    float* Cd; int ldc, cb;
    if (FUSED) {
        if (n0 < 1024)      { Cd = C0; ldc = 1024; cb = n0; }
        else if (n0 < 2048) { Cd = C1; ldc = 1024; cb = n0 - 1024; }
        else if (n0 < 4096) { Cd = C2; ldc = 2048; cb = n0 - 2048; }
        else                { Cd = C3; ldc = 2048; cb = n0 - 4096; }
    } else {
        Cd = C0; ldc = Nsingle; cb = n0;
    }
#pragma unroll
    for (int f = 0; f < 2; f++) {
        int row0 = m0 + wm * 32 + f * 16 + (lane >> 2);
#pragma unroll
        for (int p = 0; p < 8; p++) {
            int col = cb + wn * 64 + p * 8 + (lane & 3) * 2;
            *(float2*)&Cd[(size_t)row0 * ldc + col] =
                make_float2(acc[f][p][0], acc[f][p][1]);
            *(float2*)&Cd[(size_t)(row0 + 8) * ldc + col] =
                make_float2(acc[f][p][2], acc[f][p][3]);
        }
    }
}

// ---------------------------------------------------------------------------
// fp32 -> bf16 hi/lo elementwise split
// ---------------------------------------------------------------------------
__global__ void cvt_hilo(const float* __restrict__ x,
                         __nv_bfloat16* __restrict__ hi,
                         __nv_bfloat16* __restrict__ lo, int n)
{
    int i = blockIdx.x * blockDim.x + threadIdx.x;
    if (i >= n) return;
    float v = x[i];
    __nv_bfloat16 h = __float2bfloat16(v);
    hi[i] = h;
    lo[i] = __float2bfloat16(v - __bfloat162float(h));
}

// W[K,N] fp32 -> Wt[N,K] bf16 hi/lo (transpose + split)
__global__ void transpose_cvt(const float* __restrict__ W,
                              __nv_bfloat16* __restrict__ Th,
                              __nv_bfloat16* __restrict__ Tl, int K, int N)
{
    __shared__ float tile[32][33];
    int kb = blockIdx.y * 32, nb = blockIdx.x * 32;
    int tx = threadIdx.x, ty = threadIdx.y;
#pragma unroll
    for (int i = ty; i < 32; i += 8)
        tile[i][tx] = W[(size_t)(kb + i) * N + nb + tx];
    __syncthreads();
#pragma unroll
    for (int i = ty; i < 32; i += 8) {
        float v = tile[tx][i];                     // = W[kb+tx][nb+i]
        __nv_bfloat16 h = __float2bfloat16(v);
        size_t oidx = (size_t)(nb + i) * K + kb + tx;
        Th[oidx] = h;
        Tl[oidx] = __float2bfloat16(v - __bfloat162float(h));
    }
}

// ---------------------------------------------------------------------------
// Wa/Wb fused: pre-transpose to Wt[16][1024], then warp-per-token dot.
// ---------------------------------------------------------------------------
__global__ void build_wtab(const float* __restrict__ Wa,
                           const float* __restrict__ Wb,
                           float* __restrict__ Wt)
{
    int i = blockIdx.x * blockDim.x + threadIdx.x;
    if (i >= 16 * ND) return;
    int o = i / ND, k = i - o * ND;
    Wt[i] = (o < 8) ? Wa[(size_t)k * NH + o] : Wb[(size_t)k * NH + (o - 8)];
}

__global__ __launch_bounds__(256) void abproj_kernel(
    const float* __restrict__ x, const float* __restrict__ Wt,
    float* __restrict__ apre, float* __restrict__ bpre)
{
    int warp = (blockIdx.x * blockDim.x + threadIdx.x) >> 5;   // token
    int lane = threadIdx.x & 31;
    if (warp >= NTOK) return;
    const float* xr = x + (size_t)warp * ND;

    float acc[16];
#pragma unroll
    for (int o = 0; o < 16; o++) acc[o] = 0.f;

    for (int k0 = 0; k0 < ND; k0 += 32) {
        float xv = xr[k0 + lane];
#pragma unroll
        for (int o = 0; o < 16; o++)
            acc[o] += xv * Wt[o * ND + k0 + lane];
    }
#pragma unroll
    for (int o = 0; o < 16; o++) {
#pragma unroll
        for (int off = 16; off > 0; off >>= 1)
            acc[o] += __shfl_xor_sync(0xffffffffu, acc[o], off);
    }
    if (lane == 0) {
#pragma unroll
        for (int o = 0; o < 8; o++) {
            apre[(size_t)warp * 8 + o] = acc[o];
            bpre[(size_t)warp * 8 + o] = acc[8 + o];
        }
    }
}

// ---------------------------------------------------------------------------
// alpha/beta epilogue
// ---------------------------------------------------------------------------
__global__ void ab_kernel(const float* __restrict__ apre,
                          const float* __restrict__ bpre,
                          const float* __restrict__ A_log,
                          const float* __restrict__ dt_bias,
                          float* __restrict__ alpha,
                          float* __restrict__ beta)
{
    int i = blockIdx.x * blockDim.x + threadIdx.x;
    if (i >= NTOK*NH) return;
    int h = i & (NH-1);
    float xv = apre[i] + dt_bias[h];
    float sp = (xv > 20.f) ? xv : log1pf(expf(xv));
    alpha[i] = expf(-expf(A_log[h]) * sp);
    float bv = bpre[i];
    beta[i] = 2.f / (1.f + expf(-bv));
}

// ---------------------------------------------------------------------------
// Causal depthwise conv (KS=4) + SiLU (+ optional per-head l2norm)
// ---------------------------------------------------------------------------
template<int C, bool NORM>
__global__ void conv_silu_kernel(const float* __restrict__ xin,
                                 const float* __restrict__ w,
                                 float* __restrict__ out)
{
    int t  = blockIdx.x;
    int tt = t & (NT-1);
    int c4 = threadIdx.x * 4;

    float wc[4][4];
    *(float4*)wc[0] = *(const float4*)&w[(c4+0)*4];
    *(float4*)wc[1] = *(const float4*)&w[(c4+1)*4];
    *(float4*)wc[2] = *(const float4*)&w[(c4+2)*4];
    *(float4*)wc[3] = *(const float4*)&w[(c4+3)*4];

    float acc[4] = {0.f, 0.f, 0.f, 0.f};
#pragma unroll
    for (int j = 0; j < 4; j++) {
        int ts = tt - 3 + j;
        if (ts >= 0) {
            float xr[4];
            *(float4*)xr = *(const float4*)&xin[(size_t)(t-3+j)*C + c4];
#pragma unroll
            for (int ci = 0; ci < 4; ci++)
                acc[ci] += wc[ci][j] * xr[ci];
        }
    }
    float y[4];
#pragma unroll
    for (int ci = 0; ci < 4; ci++) {
        float z = acc[ci];
        y[ci] = z / (1.f + expf(-z));
    }
    if (NORM) {
        float ss = y[0]*y[0] + y[1]*y[1] + y[2]*y[2] + y[3]*y[3];
#pragma unroll
        for (int off = 16; off > 0; off >>= 1)
            ss += __shfl_xor_sync(0xffffffffu, ss, off);
        float n  = sqrtf(ss);
        float sc = 1.f / fmaxf(n, 1e-6f);
#pragma unroll
        for (int ci = 0; ci < 4; ci++) y[ci] *= sc;
    }
    *(float4*)&out[(size_t)t*C + c4] = make_float4(y[0], y[1], y[2], y[3]);
}

// ---------------------------------------------------------------------------
// Gated delta-rule scan (4-way split reductions for short dep chains)
// ---------------------------------------------------------------------------
__global__ __launch_bounds__(128, 1) void scan_kernel()
{
    const int blk = blockIdx.x;
    const int vb  = blk & 7;
    const int h   = (blk >> 3) & 7;
    const int b   = blk >> 6;
    const int vr0 = vb * 32;

    const int tid = threadIdx.x;
    const int row = tid >> 2;
    const int cg  = tid & 3;

    __shared__ float sk[32][128];
    __shared__ float sq[32][128];
    __shared__ float sv[32][32];
    __shared__ float so[32][32];
    __shared__ float sa[32];
    __shared__ float sb2[32];

    float s[32];
#pragma unroll
    for (int j = 0; j < 32; j++) s[j] = 0.f;

    const size_t tok0 = (size_t)b * NT;

    for (int c0 = 0; c0 < NT; c0 += 32) {
#pragma unroll
        for (int l = 0; l < 8; l++) {
            int id = tid + l*128;
            int st = id >> 5;
            int cq = (id & 31) * 4;
            size_t gidx = (tok0 + c0 + st) * (size_t)KEYDIM + h*KDIM + cq;
            *(float4*)&sk[st][cq] = *(const float4*)&g_k[gidx];
            *(float4*)&sq[st][cq] = *(const float4*)&g_q[gidx];
        }
#pragma unroll
        for (int l = 0; l < 2; l++) {
            int id = tid + l*128;
            int st = id >> 3;
            int vq = (id & 7) * 4;
            *(float4*)&sv[st][vq] =
                *(const float4*)&g_v[(tok0 + c0 + st) * (size_t)VALDIM + h*VDIM + vr0 + vq];
        }
        if (tid < 32)
            sa[tid] = g_alpha[(tok0 + c0 + tid) * NH + h];
        else if (tid < 64)
            sb2[tid-32] = g_beta[(tok0 + c0 + (tid-32)) * NH + h];
        __syncthreads();

        for (int i = 0; i < 32; i++) {
            float a  = sa[i];
            float bb = sb2[i];
            float vv = sv[i][row];
            float kf[32], qf[32];
            const float* kr = &sk[i][cg*32];
            const float* qr = &sq[i][cg*32];
#pragma unroll
            for (int j = 0; j < 8; j++) {
                *(float4*)&kf[j*4] = *(const float4*)&kr[j*4];
                *(float4*)&qf[j*4] = *(const float4*)&qr[j*4];
            }
            // retained = S k  (4 parallel chains)
            float r0 = 0.f, r1 = 0.f, r2 = 0.f, r3 = 0.f;
#pragma unroll
            for (int j = 0; j < 8; j++) {
                r0 += s[j*4+0] * kf[j*4+0];
                r1 += s[j*4+1] * kf[j*4+1];
                r2 += s[j*4+2] * kf[j*4+2];
                r3 += s[j*4+3] * kf[j*4+3];
            }
            float r = (r0 + r1) + (r2 + r3);
            r += __shfl_xor_sync(0xffffffffu, r, 1);
            r += __shfl_xor_sync(0xffffffffu, r, 2);
            float c = bb*vv - a*bb*r;
            // state update + output dot (4 parallel chains)
            float o0 = 0.f, o1 = 0.f, o2 = 0.f, o3 = 0.f;
#pragma unroll
            for (int j = 0; j < 8; j++) {
                s[j*4+0] = a*s[j*4+0] + c*kf[j*4+0]; o0 += s[j*4+0]*qf[j*4+0];
                s[j*4+1] = a*s[j*4+1] + c*kf[j*4+1]; o1 += s[j*4+1]*qf[j*4+1];
                s[j*4+2] = a*s[j*4+2] + c*kf[j*4+2]; o2 += s[j*4+2]*qf[j*4+2];
                s[j*4+3] = a*s[j*4+3] + c*kf[j*4+3]; o3 += s[j*4+3]*qf[j*4+3];
            }
            float o = (o0 + o1) + (o2 + o3);
            o += __shfl_xor_sync(0xffffffffu, o, 1);
            o += __shfl_xor_sync(0xffffffffu, o, 2);
            if (cg == 0) so[i][row] = o;
        }
        __syncthreads();

#pragma unroll
        for (int l = 0; l < 8; l++) {
            int id = tid + l*128;
            int st = id >> 5;
            int rr = id & 31;
            g_o[(tok0 + c0 + st) * (size_t)VALDIM + h*VDIM + vr0 + rr] = so[st][rr];
        }
    }
}

// ---------------------------------------------------------------------------
// Gating epilogue: writes bf16 hi/lo directly (feeds Wo GEMM)
// ---------------------------------------------------------------------------
__global__ void gate_kernel(const float* __restrict__ o,
                            const float* __restrict__ gate,
                            const float* __restrict__ w,
                            __nv_bfloat16* __restrict__ oh,
                            __nv_bfloat16* __restrict__ ol)
{
    int bh = blockIdx.x;
    size_t base = (size_t)bh * VDIM;
    int tid = threadIdx.x;

    float v  = o[base + tid];
    float ss = v*v;
#pragma unroll
    for (int off = 16; off > 0; off >>= 1)
        ss += __shfl_xor_sync(0xffffffffu, ss, off);
    __shared__ float red[8];
    if ((tid & 31) == 0) red[tid >> 5] = ss;
    __syncthreads();
    float tot = red[0]+red[1]+red[2]+red[3]+red[4]+red[5]+red[6]+red[7];
    float rms = rsqrtf(tot * (1.f/VDIM) + 1e-5f);

    float gv = gate[base + tid];
    float sg = gv / (1.f + expf(-gv));
    float val = v * rms * w[tid] * sg;
    __nv_bfloat16 hi = __float2bfloat16(val);
    oh[base + tid] = hi;
    ol[base + tid] = __float2bfloat16(val - __bfloat162float(hi));
}

// ---------------------------------------------------------------------------
// launch
// ---------------------------------------------------------------------------
extern "C" void kernel_launch(void* const* d_in, const int* in_sizes, int n_in,
                              void* d_out, int out_size)
{
    const float* x       = (const float*)d_in[0];
    const float* Wq      = (const float*)d_in[1];
    const float* Wk      = (const float*)d_in[2];
    const float* Wv      = (const float*)d_in[3];
    const float* Wa      = (const float*)d_in[4];
    const float* Wb      = (const float*)d_in[5];
    const float* Wg      = (const float*)d_in[6];
    const float* Wo      = (const float*)d_in[7];
    const float* A_log   = (const float*)d_in[8];
    const float* dt_bias = (const float*)d_in[9];
    const float* conv_q  = (const float*)d_in[10];
    const float* conv_k  = (const float*)d_in[11];
    const float* conv_v  = (const float*)d_in[12];
    const float* o_nw    = (const float*)d_in[13];
    float* out = (float*)d_out;

    float *qpre, *kpre, *vpre, *gatep, *obuf;
    float *apre, *bpre, *alpha, *beta, *wtab;
    __nv_bfloat16 *xh, *xl, *oh, *ol, *wth, *wtl;
    cudaGetSymbolAddress((void**)&qpre,  g_qpre);
    cudaGetSymbolAddress((void**)&kpre,  g_kpre);
    cudaGetSymbolAddress((void**)&vpre,  g_vpre);
    cudaGetSymbolAddress((void**)&gatep, g_gate);
    cudaGetSymbolAddress((void**)&obuf,  g_o);
    cudaGetSymbolAddress((void**)&apre,  g_apre);
    cudaGetSymbolAddress((void**)&bpre,  g_bpre);
    cudaGetSymbolAddress((void**)&alpha, g_alpha);
    cudaGetSymbolAddress((void**)&beta,  g_beta);
    cudaGetSymbolAddress((void**)&wtab,  g_wtab);
    cudaGetSymbolAddress((void**)&xh,    g_xh);
    cudaGetSymbolAddress((void**)&xl,    g_xl);
    cudaGetSymbolAddress((void**)&oh,    g_oh);
    cudaGetSymbolAddress((void**)&ol,    g_ol);
    cudaGetSymbolAddress((void**)&wth,   g_wth);
    cudaGetSymbolAddress((void**)&wtl,   g_wtl);
    float *q, *k, *v;
    cudaGetSymbolAddress((void**)&q, g_q);
    cudaGetSymbolAddress((void**)&k, g_k);
    cudaGetSymbolAddress((void**)&v, g_v);

    cudaFuncSetAttribute(gemm_mma<0>, cudaFuncAttributeMaxDynamicSharedMemorySize,
                         GEMM_SMEM);
    cudaFuncSetAttribute(gemm_mma<1>, cudaFuncAttributeMaxDynamicSharedMemorySize,
                         GEMM_SMEM);

    dim3 tb(32, 8);

    // Split x into bf16 hi/lo
    cvt_hilo<<<(NTOK*ND + 255)/256, 256>>>(x, xh, xl, NTOK*ND);

    // Transpose all 4 projection weights into one [6144][1024] buffer
    transpose_cvt<<<dim3(KEYDIM/32, ND/32), tb>>>(Wq, wth,                    wtl,                    ND, KEYDIM);
    transpose_cvt<<<dim3(KEYDIM/32, ND/32), tb>>>(Wk, wth + (size_t)1024*ND,  wtl + (size_t)1024*ND,  ND, KEYDIM);
    transpose_cvt<<<dim3(VALDIM/32, ND/32), tb>>>(Wv, wth + (size_t)2048*ND,  wtl + (size_t)2048*ND,  ND, VALDIM);
    transpose_cvt<<<dim3(VALDIM/32, ND/32), tb>>>(Wg, wth + (size_t)4096*ND,  wtl + (size_t)4096*ND,  ND, VALDIM);

    // One fused projection GEMM (N = 6144), epilogue scatters to 4 buffers
    gemm_mma<1><<<dim3(NPROJ/128, NTOK/128), 256, GEMM_SMEM>>>(
        xh, xl, wth, wtl, qpre, kpre, vpre, gatep, 0, ND);

    // Wa/Wb fused small-N projection
    build_wtab<<<(16*ND + 255)/256, 256>>>(Wa, Wb, wtab);
    abproj_kernel<<<(NTOK*32 + 255)/256, 256>>>(x, wtab, apre, bpre);

    ab_kernel<<<(NTOK*NH + 255)/256, 256>>>(apre, bpre, A_log, dt_bias, alpha, beta);

    conv_silu_kernel<KEYDIM, true ><<<NTOK, KEYDIM/4>>>(qpre, conv_q, q);
    conv_silu_kernel<KEYDIM, true ><<<NTOK, KEYDIM/4>>>(kpre, conv_k, k);
    conv_silu_kernel<VALDIM, false><<<NTOK, VALDIM/4>>>(vpre, conv_v, v);

    scan_kernel<<<NB*NH*8, 128>>>();

    gate_kernel<<<NTOK*NH, VDIM>>>(obuf, gatep, o_nw, oh, ol);

    // Output projection
    transpose_cvt<<<dim3(ND/32, VALDIM/32), tb>>>(Wo, wth, wtl, VALDIM, ND);
    gemm_mma<0><<<dim3(ND/128, NTOK/128), 256, GEMM_SMEM>>>(
        oh, ol, wth, wtl, out, nullptr, nullptr, nullptr, ND, VALDIM);
}

// round 6
// speedup vs baseline: 1.5889x; 1.0354x over previous
#include <cuda_runtime.h>
#include <cuda_bf16.h>
#include <math.h>
#include <stddef.h>
#include <stdint.h>

// Problem constants
#define NB 2
#define NT 2048
#define ND 1024
#define NH 8
#define KDIM 128
#define VDIM 256
#define NTOK (NB*NT)       // 4096
#define KEYDIM 1024
#define VALDIM 2048
#define NPROJ 6144         // q(1024) | k(1024) | v(2048) | g(2048)

// ---------------------------------------------------------------------------
// Scratch (static device globals; no allocation in kernel_launch)
// ---------------------------------------------------------------------------
__device__ float g_qpre[(size_t)NTOK*KEYDIM];
__device__ float g_kpre[(size_t)NTOK*KEYDIM];
__device__ float g_vpre[(size_t)NTOK*VALDIM];
__device__ float g_q   [(size_t)NTOK*KEYDIM];
__device__ float g_k   [(size_t)NTOK*KEYDIM];
__device__ float g_v   [(size_t)NTOK*VALDIM];
__device__ float g_gate[(size_t)NTOK*VALDIM];
__device__ float g_o   [(size_t)NTOK*VALDIM];
__device__ float g_apre[(size_t)NTOK*NH];
__device__ float g_bpre[(size_t)NTOK*NH];
__device__ float g_alpha[(size_t)NTOK*NH];
__device__ float g_beta [(size_t)NTOK*NH];
__device__ float g_wtab [(size_t)16*ND];

// bf16 hi/lo split scratch for tensor-core GEMMs
__device__ __align__(16) __nv_bfloat16 g_xh[(size_t)NTOK*ND];
__device__ __align__(16) __nv_bfloat16 g_xl[(size_t)NTOK*ND];
__device__ __align__(16) __nv_bfloat16 g_oh[(size_t)NTOK*VALDIM];
__device__ __align__(16) __nv_bfloat16 g_ol[(size_t)NTOK*VALDIM];
// transposed weights [N,K] bf16 hi/lo; sized for fused proj (6144x1024)
__device__ __align__(16) __nv_bfloat16 g_wth[(size_t)NPROJ*ND];
__device__ __align__(16) __nv_bfloat16 g_wtl[(size_t)NPROJ*ND];

// ---------------------------------------------------------------------------
// helpers
// ---------------------------------------------------------------------------
__device__ __forceinline__ uint32_t smem_u32(const void* p) {
    uint32_t a;
    asm("{ .reg .u64 t; cvta.to.shared.u64 t, %1; cvt.u32.u64 %0, t; }"
        : "=r"(a) : "l"(p));
    return a;
}

#define CP_ASYNC16(dst, src) \
    asm volatile("cp.async.cg.shared.global [%0], [%1], 16;" :: "r"(dst), "l"(src))
#define CP_COMMIT() asm volatile("cp.async.commit_group;")
#define CP_WAIT(n)  asm volatile("cp.async.wait_group %0;" :: "n"(n))

#define LDMX4(r, addr) \
    asm volatile("ldmatrix.sync.aligned.m8n8.x4.shared.b16 {%0,%1,%2,%3}, [%4];" \
        : "=r"((r)[0]), "=r"((r)[1]), "=r"((r)[2]), "=r"((r)[3]) : "r"(addr))

#define MMA_BF16(c, a, b) \
    asm volatile("mma.sync.aligned.m16n8k16.row.col.f32.bf16.bf16.f32 " \
        "{%0,%1,%2,%3}, {%4,%5,%6,%7}, {%8,%9}, {%0,%1,%2,%3};" \
        : "+f"((c)[0]), "+f"((c)[1]), "+f"((c)[2]), "+f"((c)[3]) \
        : "r"((a)[0]), "r"((a)[1]), "r"((a)[2]), "r"((a)[3]), \
          "r"((b)[0]), "r"((b)[1]))

// ---------------------------------------------------------------------------
// Tensor-core GEMM (legacy mma.sync, base sm_100 ISA):
//   C = (Ah+Al)[M,K] x (Bh+Bl)[N,K]^T   (bf16 hi/lo, 3 products)
// CTA tile 128x128, BK=32, 256 threads (8 warps = 4m x 2n, warp tile 32x64),
// cp.async 3-stage pipeline, 80B smem row stride (ldmatrix conflict-free).
// FUSED=1: epilogue routes 128-col tiles to 4 destination buffers.
// ---------------------------------------------------------------------------
#define TILE_B   10240            // 128 rows * 80 bytes
#define STAGE_B  (4*TILE_B)       // Ah, Al, Bh, Bl
#define GEMM_SMEM (3*STAGE_B)     // 122880 (3-stage)

__device__ __forceinline__ void g2s_chunk(
    uint32_t dbase, const __nv_bfloat16* Ah, const __nv_bfloat16* Al,
    const __nv_bfloat16* Bh, const __nv_bfloat16* Bl,
    int m0, int n0, int k0, int K, int tid)
{
    const __nv_bfloat16* srcs[4] = {
        Ah + (size_t)m0 * K + k0, Al + (size_t)m0 * K + k0,
        Bh + (size_t)n0 * K + k0, Bl + (size_t)n0 * K + k0 };
#pragma unroll
    for (int t = 0; t < 4; t++) {
        const __nv_bfloat16* src = srcs[t];
        uint32_t db = dbase + t * TILE_B;
#pragma unroll
        for (int l = 0; l < 2; l++) {
            int id  = tid + l * 256;       // 0..511
            int row = id >> 2;             // 0..127
            int q   = id & 3;              // 16B unit (8 bf16)
            CP_ASYNC16(db + row * 80 + q * 16, src + (size_t)row * K + q * 8);
        }
    }
}

template<int FUSED>
__global__ __launch_bounds__(256, 1) void gemm_mma(
    const __nv_bfloat16* __restrict__ Ah, const __nv_bfloat16* __restrict__ Al,
    const __nv_bfloat16* __restrict__ Bh, const __nv_bfloat16* __restrict__ Bl,
    float* __restrict__ C0, float* __restrict__ C1,
    float* __restrict__ C2, float* __restrict__ C3,
    int Nsingle, int K)
{
    extern __shared__ __align__(16) char smem[];
    const uint32_t sbase = smem_u32(smem);
    const int tid  = threadIdx.x;
    const int wid  = tid >> 5, lane = tid & 31;
    const int wm   = wid >> 1, wn = wid & 1;
    const int m0   = blockIdx.y * 128;
    const int n0   = blockIdx.x * 128;

    const int mat = lane >> 3;             // ldmatrix quadrant
    const int r   = lane & 7;

    float acc[2][8][4];
#pragma unroll
    for (int f = 0; f < 2; f++)
#pragma unroll
        for (int p = 0; p < 8; p++)
#pragma unroll
            for (int j = 0; j < 4; j++) acc[f][p][j] = 0.f;

    const int nc = K >> 5;

    // prologue: chunks 0,1 -> stages 0,1
    g2s_chunk(sbase, Ah, Al, Bh, Bl, m0, n0, 0, K, tid);
    CP_COMMIT();
    if (nc > 1) {
        g2s_chunk(sbase + STAGE_B, Ah, Al, Bh, Bl, m0, n0, 32, K, tid);
        CP_COMMIT();
    }

    for (int c = 0; c < nc; c++) {
        if (c + 2 < nc) {
            g2s_chunk(sbase + ((c + 2) % 3) * STAGE_B,
                      Ah, Al, Bh, Bl, m0, n0, (c + 2) << 5, K, tid);
            CP_COMMIT();
            CP_WAIT(2);
        } else if (c + 1 < nc) {
            CP_WAIT(1);
        } else {
            CP_WAIT(0);
        }
        __syncthreads();

        const uint32_t ab  = sbase + (c % 3) * STAGE_B;          // Ah tile
        const uint32_t alb = ab + TILE_B;
        const uint32_t bhb = ab + 2 * TILE_B;
        const uint32_t blb = ab + 3 * TILE_B;

#pragma unroll
        for (int ks = 0; ks < 2; ks++) {
            uint32_t fa_h[2][4], fa_l[2][4];
#pragma unroll
            for (int f = 0; f < 2; f++) {
                int row  = wm * 32 + f * 16 + ((mat & 1) << 3) + r;
                int kcol = ks * 16 + ((mat >> 1) << 3);
                uint32_t off = row * 80 + kcol * 2;
                LDMX4(fa_h[f], ab  + off);
                LDMX4(fa_l[f], alb + off);
            }
            uint32_t fb_h[8][2], fb_l[8][2];
#pragma unroll
            for (int p = 0; p < 4; p++) {
                int row  = wn * 64 + p * 16 + ((mat >> 1) << 3) + r;
                int kcol = ks * 16 + ((mat & 1) << 3);
                uint32_t off = row * 80 + kcol * 2;
                uint32_t t4[4];
                LDMX4(t4, bhb + off);
                fb_h[p*2][0] = t4[0]; fb_h[p*2][1] = t4[1];
                fb_h[p*2+1][0] = t4[2]; fb_h[p*2+1][1] = t4[3];
                LDMX4(t4, blb + off);
                fb_l[p*2][0] = t4[0]; fb_l[p*2][1] = t4[1];
                fb_l[p*2+1][0] = t4[2]; fb_l[p*2+1][1] = t4[3];
            }
#pragma unroll
            for (int f = 0; f < 2; f++)
#pragma unroll
                for (int p = 0; p < 8; p++) {
                    MMA_BF16(acc[f][p], fa_h[f], fb_h[p]);
                    MMA_BF16(acc[f][p], fa_h[f], fb_l[p]);
                    MMA_BF16(acc[f][p], fa_l[f], fb_h[p]);
                }
        }
        __syncthreads();
    }

    // epilogue: pick destination buffer / ld / column base
    float* Cd; int ldc, cb;
    if (FUSED) {
        if (n0 < 1024)      { Cd = C0; ldc = 1024; cb = n0; }
        else if (n0 < 2048) { Cd = C1; ldc = 1024; cb = n0 - 1024; }
        else if (n0 < 4096) { Cd = C2; ldc = 2048; cb = n0 - 2048; }
        else                { Cd = C3; ldc = 2048; cb = n0 - 4096; }
    } else {
        Cd = C0; ldc = Nsingle; cb = n0;
    }
#pragma unroll
    for (int f = 0; f < 2; f++) {
        int row0 = m0 + wm * 32 + f * 16 + (lane >> 2);
#pragma unroll
        for (int p = 0; p < 8; p++) {
            int col = cb + wn * 64 + p * 8 + (lane & 3) * 2;
            *(float2*)&Cd[(size_t)row0 * ldc + col] =
                make_float2(acc[f][p][0], acc[f][p][1]);
            *(float2*)&Cd[(size_t)(row0 + 8) * ldc + col] =
                make_float2(acc[f][p][2], acc[f][p][3]);
        }
    }
}

// ---------------------------------------------------------------------------
// fp32 -> bf16 hi/lo elementwise split
// ---------------------------------------------------------------------------
__global__ void cvt_hilo(const float* __restrict__ x,
                         __nv_bfloat16* __restrict__ hi,
                         __nv_bfloat16* __restrict__ lo, int n)
{
    int i = blockIdx.x * blockDim.x + threadIdx.x;
    if (i >= n) return;
    float v = x[i];
    __nv_bfloat16 h = __float2bfloat16(v);
    hi[i] = h;
    lo[i] = __float2bfloat16(v - __bfloat162float(h));
}

// W[K,N] fp32 -> Wt[N,K] bf16 hi/lo (transpose + split)
__global__ void transpose_cvt(const float* __restrict__ W,
                              __nv_bfloat16* __restrict__ Th,
                              __nv_bfloat16* __restrict__ Tl, int K, int N)
{
    __shared__ float tile[32][33];
    int kb = blockIdx.y * 32, nb = blockIdx.x * 32;
    int tx = threadIdx.x, ty = threadIdx.y;
#pragma unroll
    for (int i = ty; i < 32; i += 8)
        tile[i][tx] = W[(size_t)(kb + i) * N + nb + tx];
    __syncthreads();
#pragma unroll
    for (int i = ty; i < 32; i += 8) {
        float v = tile[tx][i];                     // = W[kb+tx][nb+i]
        __nv_bfloat16 h = __float2bfloat16(v);
        size_t oidx = (size_t)(nb + i) * K + kb + tx;
        Th[oidx] = h;
        Tl[oidx] = __float2bfloat16(v - __bfloat162float(h));
    }
}

// ---------------------------------------------------------------------------
// Wa/Wb fused: pre-transpose to Wt[16][1024], then warp-per-token dot.
// ---------------------------------------------------------------------------
__global__ void build_wtab(const float* __restrict__ Wa,
                           const float* __restrict__ Wb,
                           float* __restrict__ Wt)
{
    int i = blockIdx.x * blockDim.x + threadIdx.x;
    if (i >= 16 * ND) return;
    int o = i / ND, k = i - o * ND;
    Wt[i] = (o < 8) ? Wa[(size_t)k * NH + o] : Wb[(size_t)k * NH + (o - 8)];
}

__global__ __launch_bounds__(256) void abproj_kernel(
    const float* __restrict__ x, const float* __restrict__ Wt,
    float* __restrict__ apre, float* __restrict__ bpre)
{
    int warp = (blockIdx.x * blockDim.x + threadIdx.x) >> 5;   // token
    int lane = threadIdx.x & 31;
    if (warp >= NTOK) return;
    const float* xr = x + (size_t)warp * ND;

    float acc[16];
#pragma unroll
    for (int o = 0; o < 16; o++) acc[o] = 0.f;

    for (int k0 = 0; k0 < ND; k0 += 32) {
        float xv = xr[k0 + lane];
#pragma unroll
        for (int o = 0; o < 16; o++)
            acc[o] += xv * Wt[o * ND + k0 + lane];
    }
#pragma unroll
    for (int o = 0; o < 16; o++) {
#pragma unroll
        for (int off = 16; off > 0; off >>= 1)
            acc[o] += __shfl_xor_sync(0xffffffffu, acc[o], off);
    }
    if (lane == 0) {
#pragma unroll
        for (int o = 0; o < 8; o++) {
            apre[(size_t)warp * 8 + o] = acc[o];
            bpre[(size_t)warp * 8 + o] = acc[8 + o];
        }
    }
}

// ---------------------------------------------------------------------------
// alpha/beta epilogue
// ---------------------------------------------------------------------------
__global__ void ab_kernel(const float* __restrict__ apre,
                          const float* __restrict__ bpre,
                          const float* __restrict__ A_log,
                          const float* __restrict__ dt_bias,
                          float* __restrict__ alpha,
                          float* __restrict__ beta)
{
    int i = blockIdx.x * blockDim.x + threadIdx.x;
    if (i >= NTOK*NH) return;
    int h = i & (NH-1);
    float xv = apre[i] + dt_bias[h];
    float sp = (xv > 20.f) ? xv : log1pf(expf(xv));
    alpha[i] = expf(-expf(A_log[h]) * sp);
    float bv = bpre[i];
    beta[i] = 2.f / (1.f + expf(-bv));
}

// ---------------------------------------------------------------------------
// Causal depthwise conv (KS=4) + SiLU (+ optional per-head l2norm)
// ---------------------------------------------------------------------------
template<int C, bool NORM>
__global__ void conv_silu_kernel(const float* __restrict__ xin,
                                 const float* __restrict__ w,
                                 float* __restrict__ out)
{
    int t  = blockIdx.x;
    int tt = t & (NT-1);
    int c4 = threadIdx.x * 4;

    float wc[4][4];
    *(float4*)wc[0] = *(const float4*)&w[(c4+0)*4];
    *(float4*)wc[1] = *(const float4*)&w[(c4+1)*4];
    *(float4*)wc[2] = *(const float4*)&w[(c4+2)*4];
    *(float4*)wc[3] = *(const float4*)&w[(c4+3)*4];

    float acc[4] = {0.f, 0.f, 0.f, 0.f};
#pragma unroll
    for (int j = 0; j < 4; j++) {
        int ts = tt - 3 + j;
        if (ts >= 0) {
            float xr[4];
            *(float4*)xr = *(const float4*)&xin[(size_t)(t-3+j)*C + c4];
#pragma unroll
            for (int ci = 0; ci < 4; ci++)
                acc[ci] += wc[ci][j] * xr[ci];
        }
    }
    float y[4];
#pragma unroll
    for (int ci = 0; ci < 4; ci++) {
        float z = acc[ci];
        y[ci] = z / (1.f + expf(-z));
    }
    if (NORM) {
        float ss = y[0]*y[0] + y[1]*y[1] + y[2]*y[2] + y[3]*y[3];
#pragma unroll
        for (int off = 16; off > 0; off >>= 1)
            ss += __shfl_xor_sync(0xffffffffu, ss, off);
        float n  = sqrtf(ss);
        float sc = 1.f / fmaxf(n, 1e-6f);
#pragma unroll
        for (int ci = 0; ci < 4; ci++) y[ci] *= sc;
    }
    *(float4*)&out[(size_t)t*C + c4] = make_float4(y[0], y[1], y[2], y[3]);
}

// ---------------------------------------------------------------------------
// Gated delta-rule scan. Output reduction deferred out of the serial loop:
// each lane stores its 32-col partial o to smem; the 4-way sum happens in the
// flush phase. Removes 2 SHFLs (~52 cyc) from every step's critical path.
// Dynamic smem: sk(16K) sq(16K) sv(4K) so4(16K) sa(128) sb(128) = 52.5KB.
// ---------------------------------------------------------------------------
#define SCAN_SMEM (16384 + 16384 + 4096 + 16384 + 128 + 128)

__global__ __launch_bounds__(128, 1) void scan_kernel()
{
    extern __shared__ __align__(16) char ssm[];
    float (*sk)[128]   = (float(*)[128])(ssm);
    float (*sq)[128]   = (float(*)[128])(ssm + 16384);
    float (*sv)[32]    = (float(*)[32]) (ssm + 32768);
    float (*so4)[32][4]= (float(*)[32][4])(ssm + 36864);
    float *sa          = (float*)(ssm + 53248);
    float *sb2         = (float*)(ssm + 53376);

    const int blk = blockIdx.x;
    const int vb  = blk & 7;
    const int h   = (blk >> 3) & 7;
    const int b   = blk >> 6;
    const int vr0 = vb * 32;

    const int tid = threadIdx.x;
    const int row = tid >> 2;
    const int cg  = tid & 3;

    float s[32];
#pragma unroll
    for (int j = 0; j < 32; j++) s[j] = 0.f;

    const size_t tok0 = (size_t)b * NT;

    for (int c0 = 0; c0 < NT; c0 += 32) {
#pragma unroll
        for (int l = 0; l < 8; l++) {
            int id = tid + l*128;
            int st = id >> 5;
            int cq = (id & 31) * 4;
            size_t gidx = (tok0 + c0 + st) * (size_t)KEYDIM + h*KDIM + cq;
            *(float4*)&sk[st][cq] = *(const float4*)&g_k[gidx];
            *(float4*)&sq[st][cq] = *(const float4*)&g_q[gidx];
        }
#pragma unroll
        for (int l = 0; l < 2; l++) {
            int id = tid + l*128;
            int st = id >> 3;
            int vq = (id & 7) * 4;
            *(float4*)&sv[st][vq] =
                *(const float4*)&g_v[(tok0 + c0 + st) * (size_t)VALDIM + h*VDIM + vr0 + vq];
        }
        if (tid < 32)
            sa[tid] = g_alpha[(tok0 + c0 + tid) * NH + h];
        else if (tid < 64)
            sb2[tid-32] = g_beta[(tok0 + c0 + (tid-32)) * NH + h];
        __syncthreads();

        for (int i = 0; i < 32; i++) {
            float a  = sa[i];
            float bb = sb2[i];
            float vv = sv[i][row];
            float kf[32], qf[32];
            const float* kr = &sk[i][cg*32];
            const float* qr = &sq[i][cg*32];
#pragma unroll
            for (int j = 0; j < 8; j++) {
                *(float4*)&kf[j*4] = *(const float4*)&kr[j*4];
                *(float4*)&qf[j*4] = *(const float4*)&qr[j*4];
            }
            // retained = S k  (4 parallel chains, then 2 shfls over the 4 lanes)
            float r0 = 0.f, r1 = 0.f, r2 = 0.f, r3 = 0.f;
#pragma unroll
            for (int j = 0; j < 8; j++) {
                r0 += s[j*4+0] * kf[j*4+0];
                r1 += s[j*4+1] * kf[j*4+1];
                r2 += s[j*4+2] * kf[j*4+2];
                r3 += s[j*4+3] * kf[j*4+3];
            }
            float r = (r0 + r1) + (r2 + r3);
            r += __shfl_xor_sync(0xffffffffu, r, 1);
            r += __shfl_xor_sync(0xffffffffu, r, 2);
            float c = bb*vv - a*bb*r;
            // state update + per-lane partial output (NO shfl here)
            float o0 = 0.f, o1 = 0.f, o2 = 0.f, o3 = 0.f;
#pragma unroll
            for (int j = 0; j < 8; j++) {
                s[j*4+0] = a*s[j*4+0] + c*kf[j*4+0]; o0 += s[j*4+0]*qf[j*4+0];
                s[j*4+1] = a*s[j*4+1] + c*kf[j*4+1]; o1 += s[j*4+1]*qf[j*4+1];
                s[j*4+2] = a*s[j*4+2] + c*kf[j*4+2]; o2 += s[j*4+2]*qf[j*4+2];
                s[j*4+3] = a*s[j*4+3] + c*kf[j*4+3]; o3 += s[j*4+3]*qf[j*4+3];
            }
            so4[i][row][cg] = (o0 + o1) + (o2 + o3);
        }
        __syncthreads();

        // flush: 4-way partial sum + coalesced store
#pragma unroll
        for (int l = 0; l < 8; l++) {
            int id = tid + l*128;
            int st = id >> 5;
            int rr = id & 31;
            float4 p = *(float4*)&so4[st][rr][0];
            g_o[(tok0 + c0 + st) * (size_t)VALDIM + h*VDIM + vr0 + rr] =
                (p.x + p.y) + (p.z + p.w);
        }
    }
}

// ---------------------------------------------------------------------------
// Gating epilogue: writes bf16 hi/lo directly (feeds Wo GEMM)
// ---------------------------------------------------------------------------
__global__ void gate_kernel(const float* __restrict__ o,
                            const float* __restrict__ gate,
                            const float* __restrict__ w,
                            __nv_bfloat16* __restrict__ oh,
                            __nv_bfloat16* __restrict__ ol)
{
    int bh = blockIdx.x;
    size_t base = (size_t)bh * VDIM;
    int tid = threadIdx.x;

    float v  = o[base + tid];
    float ss = v*v;
#pragma unroll
    for (int off = 16; off > 0; off >>= 1)
        ss += __shfl_xor_sync(0xffffffffu, ss, off);
    __shared__ float red[8];
    if ((tid & 31) == 0) red[tid >> 5] = ss;
    __syncthreads();
    float tot = red[0]+red[1]+red[2]+red[3]+red[4]+red[5]+red[6]+red[7];
    float rms = rsqrtf(tot * (1.f/VDIM) + 1e-5f);

    float gv = gate[base + tid];
    float sg = gv / (1.f + expf(-gv));
    float val = v * rms * w[tid] * sg;
    __nv_bfloat16 hi = __float2bfloat16(val);
    oh[base + tid] = hi;
    ol[base + tid] = __float2bfloat16(val - __bfloat162float(hi));
}

// ---------------------------------------------------------------------------
// launch
// ---------------------------------------------------------------------------
extern "C" void kernel_launch(void* const* d_in, const int* in_sizes, int n_in,
                              void* d_out, int out_size)
{
    const float* x       = (const float*)d_in[0];
    const float* Wq      = (const float*)d_in[1];
    const float* Wk      = (const float*)d_in[2];
    const float* Wv      = (const float*)d_in[3];
    const float* Wa      = (const float*)d_in[4];
    const float* Wb      = (const float*)d_in[5];
    const float* Wg      = (const float*)d_in[6];
    const float* Wo      = (const float*)d_in[7];
    const float* A_log   = (const float*)d_in[8];
    const float* dt_bias = (const float*)d_in[9];
    const float* conv_q  = (const float*)d_in[10];
    const float* conv_k  = (const float*)d_in[11];
    const float* conv_v  = (const float*)d_in[12];
    const float* o_nw    = (const float*)d_in[13];
    float* out = (float*)d_out;

    float *qpre, *kpre, *vpre, *gatep, *obuf;
    float *apre, *bpre, *alpha, *beta, *wtab;
    __nv_bfloat16 *xh, *xl, *oh, *ol, *wth, *wtl;
    cudaGetSymbolAddress((void**)&qpre,  g_qpre);
    cudaGetSymbolAddress((void**)&kpre,  g_kpre);
    cudaGetSymbolAddress((void**)&vpre,  g_vpre);
    cudaGetSymbolAddress((void**)&gatep, g_gate);
    cudaGetSymbolAddress((void**)&obuf,  g_o);
    cudaGetSymbolAddress((void**)&apre,  g_apre);
    cudaGetSymbolAddress((void**)&bpre,  g_bpre);
    cudaGetSymbolAddress((void**)&alpha, g_alpha);
    cudaGetSymbolAddress((void**)&beta,  g_beta);
    cudaGetSymbolAddress((void**)&wtab,  g_wtab);
    cudaGetSymbolAddress((void**)&xh,    g_xh);
    cudaGetSymbolAddress((void**)&xl,    g_xl);
    cudaGetSymbolAddress((void**)&oh,    g_oh);
    cudaGetSymbolAddress((void**)&ol,    g_ol);
    cudaGetSymbolAddress((void**)&wth,   g_wth);
    cudaGetSymbolAddress((void**)&wtl,   g_wtl);
    float *q, *k, *v;
    cudaGetSymbolAddress((void**)&q, g_q);
    cudaGetSymbolAddress((void**)&k, g_k);
    cudaGetSymbolAddress((void**)&v, g_v);

    cudaFuncSetAttribute(gemm_mma<0>, cudaFuncAttributeMaxDynamicSharedMemorySize,
                         GEMM_SMEM);
    cudaFuncSetAttribute(gemm_mma<1>, cudaFuncAttributeMaxDynamicSharedMemorySize,
                         GEMM_SMEM);
    cudaFuncSetAttribute(scan_kernel, cudaFuncAttributeMaxDynamicSharedMemorySize,
                         SCAN_SMEM);

    dim3 tb(32, 8);

    // Split x into bf16 hi/lo
    cvt_hilo<<<(NTOK*ND + 255)/256, 256>>>(x, xh, xl, NTOK*ND);

    // Transpose all 4 projection weights into one [6144][1024] buffer
    transpose_cvt<<<dim3(KEYDIM/32, ND/32), tb>>>(Wq, wth,                    wtl,                    ND, KEYDIM);
    transpose_cvt<<<dim3(KEYDIM/32, ND/32), tb>>>(Wk, wth + (size_t)1024*ND,  wtl + (size_t)1024*ND,  ND, KEYDIM);
    transpose_cvt<<<dim3(VALDIM/32, ND/32), tb>>>(Wv, wth + (size_t)2048*ND,  wtl + (size_t)2048*ND,  ND, VALDIM);
    transpose_cvt<<<dim3(VALDIM/32, ND/32), tb>>>(Wg, wth + (size_t)4096*ND,  wtl + (size_t)4096*ND,  ND, VALDIM);

    // One fused projection GEMM (N = 6144), epilogue scatters to 4 buffers
    gemm_mma<1><<<dim3(NPROJ/128, NTOK/128), 256, GEMM_SMEM>>>(
        xh, xl, wth, wtl, qpre, kpre, vpre, gatep, 0, ND);

    // Wa/Wb fused small-N projection
    build_wtab<<<(16*ND + 255)/256, 256>>>(Wa, Wb, wtab);
    abproj_kernel<<<(NTOK*32 + 255)/256, 256>>>(x, wtab, apre, bpre);

    ab_kernel<<<(NTOK*NH + 255)/256, 256>>>(apre, bpre, A_log, dt_bias, alpha, beta);

    conv_silu_kernel<KEYDIM, true ><<<NTOK, KEYDIM/4>>>(qpre, conv_q, q);
    conv_silu_kernel<KEYDIM, true ><<<NTOK, KEYDIM/4>>>(kpre, conv_k, k);
    conv_silu_kernel<VALDIM, false><<<NTOK, VALDIM/4>>>(vpre, conv_v, v);

    scan_kernel<<<NB*NH*8, 128, SCAN_SMEM>>>();

    gate_kernel<<<NTOK*NH, VDIM>>>(obuf, gatep, o_nw, oh, ol);

    // Output projection
    transpose_cvt<<<dim3(ND/32, VALDIM/32), tb>>>(Wo, wth, wtl, VALDIM, ND);
    gemm_mma<0><<<dim3(ND/128, NTOK/128), 256, GEMM_SMEM>>>(
        oh, ol, wth, wtl, out, nullptr, nullptr, nullptr, ND, VALDIM);
}